// round 5
// baseline (speedup 1.0000x reference)
#include <cuda_runtime.h>

// ChamferDistance: N=4, P1=P2=8192, D=3.
// out layout (float32): [cham_x (N*P)] [cham_y (N*P)] [idx_x (N*P)] [idx_y (N*P)]
//
// Distance arithmetic is a bit-exact emulation of the JAX reference:
//   sa = ((x*x) + (y*y)) + (z*z)          (separate roundings, left-to-right)
//   dot = fma(a2,b2, fma(a1,b1, rnd(a0*b0)))   (ascending-k fp32 fma chain)
//   d2  = (sa + sb) - 2*dot               (2*dot exact; one rounding per add)
// Argmin: strict < with ascending j => first-occurrence, matching jnp.argmin.

#define NB      4
#define NP      8192
#define TILE    1024     // reference points staged in shared per iteration
#define QPT     2        // queries per thread
#define THREADS 256
#define QPB     (THREADS * QPT)   // 512 queries per block

__device__ __forceinline__ float norm2_ref(float x, float y, float z) {
    // ((x*x) + (y*y)) + (z*z), each op individually rounded (no FMA fusion)
    float xx = __fmul_rn(x, x);
    float yy = __fmul_rn(y, y);
    float zz = __fmul_rn(z, z);
    return __fadd_rn(__fadd_rn(xx, yy), zz);
}

__global__ __launch_bounds__(THREADS, 2)
void chamfer_nn_kernel(const float* __restrict__ x,
                       const float* __restrict__ y,
                       float* __restrict__ out) {
    const int n   = blockIdx.y;   // batch
    const int dir = blockIdx.z;   // 0: x->y, 1: y->x

    const float* A = (dir == 0) ? x : y;   // query cloud
    const float* B = (dir == 0) ? y : x;   // reference cloud

    // Output slices: cham_x | cham_y | idx_x | idx_y
    float* outD = out + (dir == 0 ? 0 : NB * NP) + n * NP;
    float* outI = out + 2 * NB * NP + (dir == 0 ? 0 : NB * NP) + n * NP;

    __shared__ float4 sB[TILE];

    const int q0 = blockIdx.x * QPB + threadIdx.x;

    // Load this thread's query points into registers
    float qx[QPT], qy[QPT], qz[QPT], sq[QPT];
    float best[QPT];
    int   bidx[QPT];
#pragma unroll
    for (int t = 0; t < QPT; t++) {
        const int q = q0 + t * THREADS;
        const float* p = A + ((long)n * NP + q) * 3;
        qx[t] = p[0];
        qy[t] = p[1];
        qz[t] = p[2];
        sq[t] = norm2_ref(qx[t], qy[t], qz[t]);
        best[t] = __int_as_float(0x7f800000);   // +inf
        bidx[t] = 0;
    }

    for (int base = 0; base < NP; base += TILE) {
        __syncthreads();
        // Stage TILE reference points (with precomputed |b|^2) into shared
        for (int j = threadIdx.x; j < TILE; j += THREADS) {
            const float* p = B + ((long)n * NP + base + j) * 3;
            const float bx = p[0], by = p[1], bz = p[2];
            sB[j] = make_float4(bx, by, bz, norm2_ref(bx, by, bz));
        }
        __syncthreads();

#pragma unroll 8
        for (int j = 0; j < TILE; j++) {
            const float4 b = sB[j];   // broadcast LDS.128, conflict-free
#pragma unroll
            for (int t = 0; t < QPT; t++) {
                // dot, ascending-k fp32 fma chain (matches XLA contraction)
                const float dot = __fmaf_rn(qz[t], b.z,
                                  __fmaf_rn(qy[t], b.y,
                                  __fmul_rn(qx[t], b.x)));
                const float ss   = __fadd_rn(sq[t], b.w);       // (sa + sb), rounded
                const float m2d  = __fmul_rn(dot, -2.0f);       // exact (x2 scaling)
                const float d2   = __fadd_rn(ss, m2d);          // one rounding
                if (d2 < best[t]) {                             // first-occurrence argmin
                    best[t] = d2;
                    bidx[t] = base + j;
                }
            }
        }
    }

#pragma unroll
    for (int t = 0; t < QPT; t++) {
        const int q = q0 + t * THREADS;
        outD[q] = best[t];
        outI[q] = (float)bidx[t];
    }
}

extern "C" void kernel_launch(void* const* d_in, const int* in_sizes, int n_in,
                              void* d_out, int out_size) {
    const float* x = (const float*)d_in[0];
    const float* y = (const float*)d_in[1];
    float* out = (float*)d_out;

    dim3 grid(NP / QPB, NB, 2);   // 16 x 4 x 2 = 128 blocks, one wave
    dim3 block(THREADS);
    chamfer_nn_kernel<<<grid, block>>>(x, y, out);
}

// round 6
// speedup vs baseline: 1.2215x; 1.2215x over previous
#include <cuda_runtime.h>

// ChamferDistance: N=4, P1=P2=8192, D=3.
// out (float32): [cham_x (N*P)] [cham_y (N*P)] [idx_x (N*P)] [idx_y (N*P)]
//
// Bit-exact emulation of the JAX reference (identical to the round-5 passing
// kernel's arithmetic, now vectorized with Blackwell packed f32x2 ops):
//   sq  = ((x*x)+(y*y))+(z*z)                     (separate roundings)
//   m   = fma(-2z,bz, fma(-2y,by, rnd(-2x*bx)))   == -2*dot bitwise
//   d2  = rnd( rnd(sq + bw) + m )
// Argmin: strict <, ascending j (split halves merged in ascending order)
// => first-occurrence, matching jnp.argmin.

#define NB      4
#define NP      8192
#define THREADS 64
#define QPT     4
#define QPB     (THREADS * QPT)     // 256 queries per block
#define RSPLIT  4                   // reference range split
#define RLEN    (NP / RSPLIT)       // 2048
#define TILE    512                 // ref points staged in shared per iter
#define NQ_TOT  (2 * NB * NP)       // 65536 total queries (both directions)

// Candidate scratch: [rsplit][query-slot]
__device__ float g_cd[RSPLIT * NQ_TOT];
__device__ int   g_ci[RSPLIT * NQ_TOT];

typedef unsigned long long u64t;

__device__ __forceinline__ u64t pack2(float lo, float hi) {
    u64t r;
    asm("mov.b64 %0, {%1, %2};" : "=l"(r) : "f"(lo), "f"(hi));
    return r;
}
__device__ __forceinline__ void unpack2(u64t v, float& lo, float& hi) {
    asm("mov.b64 {%0, %1}, %2;" : "=f"(lo), "=f"(hi) : "l"(v));
}
__device__ __forceinline__ u64t mul2(u64t a, u64t b) {
    u64t r;
    asm("mul.rn.f32x2 %0, %1, %2;" : "=l"(r) : "l"(a), "l"(b));
    return r;
}
__device__ __forceinline__ u64t fma2(u64t a, u64t b, u64t c) {
    u64t r;
    asm("fma.rn.f32x2 %0, %1, %2, %3;" : "=l"(r) : "l"(a), "l"(b), "l"(c));
    return r;
}
__device__ __forceinline__ u64t add2(u64t a, u64t b) {
    u64t r;
    asm("add.rn.f32x2 %0, %1, %2;" : "=l"(r) : "l"(a), "l"(b));
    return r;
}

__device__ __forceinline__ float norm2_ref(float x, float y, float z) {
    // ((x*x)+(y*y))+(z*z), each op individually rounded
    float xx = __fmul_rn(x, x);
    float yy = __fmul_rn(y, y);
    float zz = __fmul_rn(z, z);
    return __fadd_rn(__fadd_rn(xx, yy), zz);
}

__global__ __launch_bounds__(THREADS)
void chamfer_main_kernel(const float* __restrict__ x,
                         const float* __restrict__ y) {
    const int n   = blockIdx.y;            // batch
    const int dir = blockIdx.z / RSPLIT;   // 0: x->y, 1: y->x
    const int h   = blockIdx.z % RSPLIT;   // reference half-range id

    const float* A = (dir == 0) ? x : y;   // query cloud
    const float* B = (dir == 0) ? y : x;   // reference cloud

    // Shared: duplicated components, 32B per ref point:
    // sDup[2j]   = (bx, bx, by, by)
    // sDup[2j+1] = (bz, bz, bw, bw)
    __shared__ float4 sDup[TILE * 2];

    const int tid = threadIdx.x;
    const int qbase = blockIdx.x * QPB + tid;

    // Per-thread query state: 4 queries, packed pairwise (t0,t1) and (t2,t3)
    u64t qx2p[2], qy2p[2], qz2p[2], sqp[2];
    {
        float qx2[QPT], qy2[QPT], qz2[QPT], sq[QPT];
#pragma unroll
        for (int t = 0; t < QPT; t++) {
            const int q = qbase + t * THREADS;
            const float* p = A + ((long)n * NP + q) * 3;
            const float px = p[0], py = p[1], pz = p[2];
            qx2[t] = -2.0f * px;              // exact scaling
            qy2[t] = -2.0f * py;
            qz2[t] = -2.0f * pz;
            sq[t]  = norm2_ref(px, py, pz);
        }
        qx2p[0] = pack2(qx2[0], qx2[1]);  qx2p[1] = pack2(qx2[2], qx2[3]);
        qy2p[0] = pack2(qy2[0], qy2[1]);  qy2p[1] = pack2(qy2[2], qy2[3]);
        qz2p[0] = pack2(qz2[0], qz2[1]);  qz2p[1] = pack2(qz2[2], qz2[3]);
        sqp[0]  = pack2(sq[0],  sq[1]);   sqp[1]  = pack2(sq[2],  sq[3]);
    }

    float best[QPT];
    int   bidx[QPT];
#pragma unroll
    for (int t = 0; t < QPT; t++) {
        best[t] = __int_as_float(0x7f800000);  // +inf
        bidx[t] = 0;
    }

    const u64t* sU = reinterpret_cast<const u64t*>(sDup);

    const int r0 = h * RLEN;
    for (int base = r0; base < r0 + RLEN; base += TILE) {
        __syncthreads();
        for (int m = tid; m < TILE; m += THREADS) {
            const float* p = B + ((long)n * NP + base + m) * 3;
            const float bx = p[0], by = p[1], bz = p[2];
            const float bw = norm2_ref(bx, by, bz);
            sDup[2 * m]     = make_float4(bx, bx, by, by);
            sDup[2 * m + 1] = make_float4(bz, bz, bw, bw);
        }
        __syncthreads();

#pragma unroll 8
        for (int j = 0; j < TILE; j++) {
            // broadcast LDS.128 x2: (bxx, byy), (bzz, bww)
            const u64t bxx = sU[4 * j + 0];
            const u64t byy = sU[4 * j + 1];
            const u64t bzz = sU[4 * j + 2];
            const u64t bww = sU[4 * j + 3];
            const int  jg  = base + j;
#pragma unroll
            for (int pp = 0; pp < 2; pp++) {
                u64t m  = mul2(qx2p[pp], bxx);        // rnd(-2x*bx) pairwise
                m       = fma2(qy2p[pp], byy, m);
                m       = fma2(qz2p[pp], bzz, m);     // == -2*dot bitwise
                u64t ss = add2(sqp[pp], bww);         // rnd(sq + bw)
                u64t d2 = add2(ss, m);                // rnd(ss - 2*dot)
                float d0, d1;
                unpack2(d2, d0, d1);
                if (d0 < best[2 * pp]) {
                    best[2 * pp] = d0;  bidx[2 * pp] = jg;
                }
                if (d1 < best[2 * pp + 1]) {
                    best[2 * pp + 1] = d1;  bidx[2 * pp + 1] = jg;
                }
            }
        }
    }

    // Candidate slot: dist layout index = dir*NB*NP + n*NP + q
#pragma unroll
    for (int t = 0; t < QPT; t++) {
        const int q = qbase + t * THREADS;
        const int slot = dir * (NB * NP) + n * NP + q;
        g_cd[h * NQ_TOT + slot] = best[t];
        g_ci[h * NQ_TOT + slot] = bidx[t];
    }
}

__global__ void chamfer_merge_kernel(float* __restrict__ out) {
    const int t = blockIdx.x * blockDim.x + threadIdx.x;
    if (t >= NQ_TOT) return;
    float best = g_cd[t];
    int   bi   = g_ci[t];
#pragma unroll
    for (int h = 1; h < RSPLIT; h++) {
        const float d = g_cd[h * NQ_TOT + t];
        if (d < best) {            // strict <, ascending h => first occurrence
            best = d;
            bi   = g_ci[h * NQ_TOT + t];
        }
    }
    out[t]          = best;        // cham_x | cham_y section
    out[NQ_TOT + t] = (float)bi;   // idx_x  | idx_y  section
}

extern "C" void kernel_launch(void* const* d_in, const int* in_sizes, int n_in,
                              void* d_out, int out_size) {
    const float* x = (const float*)d_in[0];
    const float* y = (const float*)d_in[1];
    float* out = (float*)d_out;

    dim3 grid(NP / QPB, NB, 2 * RSPLIT);   // 32 x 4 x 8 = 1024 blocks
    chamfer_main_kernel<<<grid, THREADS>>>(x, y);
    chamfer_merge_kernel<<<NQ_TOT / 256, 256>>>(out);
}

// round 7
// speedup vs baseline: 1.2237x; 1.0019x over previous
#include <cuda_runtime.h>

// ChamferDistance: N=4, P1=P2=8192, D=3.
// out (float32): [cham_x (N*P)] [cham_y (N*P)] [idx_x (N*P)] [idx_y (N*P)]
//
// Bit-exact emulation of the JAX reference (identical to the round-5 passing
// kernel's arithmetic, now vectorized with Blackwell packed f32x2 ops):
//   sq  = ((x*x)+(y*y))+(z*z)                     (separate roundings)
//   m   = fma(-2z,bz, fma(-2y,by, rnd(-2x*bx)))   == -2*dot bitwise
//   d2  = rnd( rnd(sq + bw) + m )
// Argmin: strict <, ascending j (split halves merged in ascending order)
// => first-occurrence, matching jnp.argmin.

#define NB      4
#define NP      8192
#define THREADS 64
#define QPT     4
#define QPB     (THREADS * QPT)     // 256 queries per block
#define RSPLIT  4                   // reference range split
#define RLEN    (NP / RSPLIT)       // 2048
#define TILE    512                 // ref points staged in shared per iter
#define NQ_TOT  (2 * NB * NP)       // 65536 total queries (both directions)

// Candidate scratch: [rsplit][query-slot]
__device__ float g_cd[RSPLIT * NQ_TOT];
__device__ int   g_ci[RSPLIT * NQ_TOT];

typedef unsigned long long u64t;

__device__ __forceinline__ u64t pack2(float lo, float hi) {
    u64t r;
    asm("mov.b64 %0, {%1, %2};" : "=l"(r) : "f"(lo), "f"(hi));
    return r;
}
__device__ __forceinline__ void unpack2(u64t v, float& lo, float& hi) {
    asm("mov.b64 {%0, %1}, %2;" : "=f"(lo), "=f"(hi) : "l"(v));
}
__device__ __forceinline__ u64t mul2(u64t a, u64t b) {
    u64t r;
    asm("mul.rn.f32x2 %0, %1, %2;" : "=l"(r) : "l"(a), "l"(b));
    return r;
}
__device__ __forceinline__ u64t fma2(u64t a, u64t b, u64t c) {
    u64t r;
    asm("fma.rn.f32x2 %0, %1, %2, %3;" : "=l"(r) : "l"(a), "l"(b), "l"(c));
    return r;
}
__device__ __forceinline__ u64t add2(u64t a, u64t b) {
    u64t r;
    asm("add.rn.f32x2 %0, %1, %2;" : "=l"(r) : "l"(a), "l"(b));
    return r;
}

__device__ __forceinline__ float norm2_ref(float x, float y, float z) {
    // ((x*x)+(y*y))+(z*z), each op individually rounded
    float xx = __fmul_rn(x, x);
    float yy = __fmul_rn(y, y);
    float zz = __fmul_rn(z, z);
    return __fadd_rn(__fadd_rn(xx, yy), zz);
}

__global__ __launch_bounds__(THREADS)
void chamfer_main_kernel(const float* __restrict__ x,
                         const float* __restrict__ y) {
    const int n   = blockIdx.y;            // batch
    const int dir = blockIdx.z / RSPLIT;   // 0: x->y, 1: y->x
    const int h   = blockIdx.z % RSPLIT;   // reference half-range id

    const float* A = (dir == 0) ? x : y;   // query cloud
    const float* B = (dir == 0) ? y : x;   // reference cloud

    // Shared: duplicated components, 32B per ref point:
    // sDup[2j]   = (bx, bx, by, by)
    // sDup[2j+1] = (bz, bz, bw, bw)
    __shared__ float4 sDup[TILE * 2];

    const int tid = threadIdx.x;
    const int qbase = blockIdx.x * QPB + tid;

    // Per-thread query state: 4 queries, packed pairwise (t0,t1) and (t2,t3)
    u64t qx2p[2], qy2p[2], qz2p[2], sqp[2];
    {
        float qx2[QPT], qy2[QPT], qz2[QPT], sq[QPT];
#pragma unroll
        for (int t = 0; t < QPT; t++) {
            const int q = qbase + t * THREADS;
            const float* p = A + ((long)n * NP + q) * 3;
            const float px = p[0], py = p[1], pz = p[2];
            qx2[t] = -2.0f * px;              // exact scaling
            qy2[t] = -2.0f * py;
            qz2[t] = -2.0f * pz;
            sq[t]  = norm2_ref(px, py, pz);
        }
        qx2p[0] = pack2(qx2[0], qx2[1]);  qx2p[1] = pack2(qx2[2], qx2[3]);
        qy2p[0] = pack2(qy2[0], qy2[1]);  qy2p[1] = pack2(qy2[2], qy2[3]);
        qz2p[0] = pack2(qz2[0], qz2[1]);  qz2p[1] = pack2(qz2[2], qz2[3]);
        sqp[0]  = pack2(sq[0],  sq[1]);   sqp[1]  = pack2(sq[2],  sq[3]);
    }

    float best[QPT];
    int   bidx[QPT];
#pragma unroll
    for (int t = 0; t < QPT; t++) {
        best[t] = __int_as_float(0x7f800000);  // +inf
        bidx[t] = 0;
    }

    const u64t* sU = reinterpret_cast<const u64t*>(sDup);

    const int r0 = h * RLEN;
    for (int base = r0; base < r0 + RLEN; base += TILE) {
        __syncthreads();
        for (int m = tid; m < TILE; m += THREADS) {
            const float* p = B + ((long)n * NP + base + m) * 3;
            const float bx = p[0], by = p[1], bz = p[2];
            const float bw = norm2_ref(bx, by, bz);
            sDup[2 * m]     = make_float4(bx, bx, by, by);
            sDup[2 * m + 1] = make_float4(bz, bz, bw, bw);
        }
        __syncthreads();

#pragma unroll 8
        for (int j = 0; j < TILE; j++) {
            // broadcast LDS.128 x2: (bxx, byy), (bzz, bww)
            const u64t bxx = sU[4 * j + 0];
            const u64t byy = sU[4 * j + 1];
            const u64t bzz = sU[4 * j + 2];
            const u64t bww = sU[4 * j + 3];
            const int  jg  = base + j;
#pragma unroll
            for (int pp = 0; pp < 2; pp++) {
                u64t m  = mul2(qx2p[pp], bxx);        // rnd(-2x*bx) pairwise
                m       = fma2(qy2p[pp], byy, m);
                m       = fma2(qz2p[pp], bzz, m);     // == -2*dot bitwise
                u64t ss = add2(sqp[pp], bww);         // rnd(sq + bw)
                u64t d2 = add2(ss, m);                // rnd(ss - 2*dot)
                float d0, d1;
                unpack2(d2, d0, d1);
                if (d0 < best[2 * pp]) {
                    best[2 * pp] = d0;  bidx[2 * pp] = jg;
                }
                if (d1 < best[2 * pp + 1]) {
                    best[2 * pp + 1] = d1;  bidx[2 * pp + 1] = jg;
                }
            }
        }
    }

    // Candidate slot: dist layout index = dir*NB*NP + n*NP + q
#pragma unroll
    for (int t = 0; t < QPT; t++) {
        const int q = qbase + t * THREADS;
        const int slot = dir * (NB * NP) + n * NP + q;
        g_cd[h * NQ_TOT + slot] = best[t];
        g_ci[h * NQ_TOT + slot] = bidx[t];
    }
}

__global__ void chamfer_merge_kernel(float* __restrict__ out) {
    const int t = blockIdx.x * blockDim.x + threadIdx.x;
    if (t >= NQ_TOT) return;
    float best = g_cd[t];
    int   bi   = g_ci[t];
#pragma unroll
    for (int h = 1; h < RSPLIT; h++) {
        const float d = g_cd[h * NQ_TOT + t];
        if (d < best) {            // strict <, ascending h => first occurrence
            best = d;
            bi   = g_ci[h * NQ_TOT + t];
        }
    }
    out[t]          = best;        // cham_x | cham_y section
    out[NQ_TOT + t] = (float)bi;   // idx_x  | idx_y  section
}

extern "C" void kernel_launch(void* const* d_in, const int* in_sizes, int n_in,
                              void* d_out, int out_size) {
    const float* x = (const float*)d_in[0];
    const float* y = (const float*)d_in[1];
    float* out = (float*)d_out;

    dim3 grid(NP / QPB, NB, 2 * RSPLIT);   // 32 x 4 x 8 = 1024 blocks
    chamfer_main_kernel<<<grid, THREADS>>>(x, y);
    chamfer_merge_kernel<<<NQ_TOT / 256, 256>>>(out);
}

// round 10
// speedup vs baseline: 1.2256x; 1.0015x over previous
#include <cuda_runtime.h>

// ChamferDistance: N=4, P1=P2=8192, D=3.
// out (float32): [cham_x (N*P)] [cham_y (N*P)] [idx_x (N*P)] [idx_y (N*P)]
//
// Bit-exact emulation of the JAX reference (identical to the round-5 passing
// kernel's arithmetic, now vectorized with Blackwell packed f32x2 ops):
//   sq  = ((x*x)+(y*y))+(z*z)                     (separate roundings)
//   m   = fma(-2z,bz, fma(-2y,by, rnd(-2x*bx)))   == -2*dot bitwise
//   d2  = rnd( rnd(sq + bw) + m )
// Argmin: strict <, ascending j (split halves merged in ascending order)
// => first-occurrence, matching jnp.argmin.

#define NB      4
#define NP      8192
#define THREADS 64
#define QPT     4
#define QPB     (THREADS * QPT)     // 256 queries per block
#define RSPLIT  4                   // reference range split
#define RLEN    (NP / RSPLIT)       // 2048
#define TILE    512                 // ref points staged in shared per iter
#define NQ_TOT  (2 * NB * NP)       // 65536 total queries (both directions)

// Candidate scratch: [rsplit][query-slot]
__device__ float g_cd[RSPLIT * NQ_TOT];
__device__ int   g_ci[RSPLIT * NQ_TOT];

typedef unsigned long long u64t;

__device__ __forceinline__ u64t pack2(float lo, float hi) {
    u64t r;
    asm("mov.b64 %0, {%1, %2};" : "=l"(r) : "f"(lo), "f"(hi));
    return r;
}
__device__ __forceinline__ void unpack2(u64t v, float& lo, float& hi) {
    asm("mov.b64 {%0, %1}, %2;" : "=f"(lo), "=f"(hi) : "l"(v));
}
__device__ __forceinline__ u64t mul2(u64t a, u64t b) {
    u64t r;
    asm("mul.rn.f32x2 %0, %1, %2;" : "=l"(r) : "l"(a), "l"(b));
    return r;
}
__device__ __forceinline__ u64t fma2(u64t a, u64t b, u64t c) {
    u64t r;
    asm("fma.rn.f32x2 %0, %1, %2, %3;" : "=l"(r) : "l"(a), "l"(b), "l"(c));
    return r;
}
__device__ __forceinline__ u64t add2(u64t a, u64t b) {
    u64t r;
    asm("add.rn.f32x2 %0, %1, %2;" : "=l"(r) : "l"(a), "l"(b));
    return r;
}

__device__ __forceinline__ float norm2_ref(float x, float y, float z) {
    // ((x*x)+(y*y))+(z*z), each op individually rounded
    float xx = __fmul_rn(x, x);
    float yy = __fmul_rn(y, y);
    float zz = __fmul_rn(z, z);
    return __fadd_rn(__fadd_rn(xx, yy), zz);
}

__global__ __launch_bounds__(THREADS)
void chamfer_main_kernel(const float* __restrict__ x,
                         const float* __restrict__ y) {
    const int n   = blockIdx.y;            // batch
    const int dir = blockIdx.z / RSPLIT;   // 0: x->y, 1: y->x
    const int h   = blockIdx.z % RSPLIT;   // reference half-range id

    const float* A = (dir == 0) ? x : y;   // query cloud
    const float* B = (dir == 0) ? y : x;   // reference cloud

    // Shared: duplicated components, 32B per ref point:
    // sDup[2j]   = (bx, bx, by, by)
    // sDup[2j+1] = (bz, bz, bw, bw)
    __shared__ float4 sDup[TILE * 2];

    const int tid = threadIdx.x;
    const int qbase = blockIdx.x * QPB + tid;

    // Per-thread query state: 4 queries, packed pairwise (t0,t1) and (t2,t3)
    u64t qx2p[2], qy2p[2], qz2p[2], sqp[2];
    {
        float qx2[QPT], qy2[QPT], qz2[QPT], sq[QPT];
#pragma unroll
        for (int t = 0; t < QPT; t++) {
            const int q = qbase + t * THREADS;
            const float* p = A + ((long)n * NP + q) * 3;
            const float px = p[0], py = p[1], pz = p[2];
            qx2[t] = -2.0f * px;              // exact scaling
            qy2[t] = -2.0f * py;
            qz2[t] = -2.0f * pz;
            sq[t]  = norm2_ref(px, py, pz);
        }
        qx2p[0] = pack2(qx2[0], qx2[1]);  qx2p[1] = pack2(qx2[2], qx2[3]);
        qy2p[0] = pack2(qy2[0], qy2[1]);  qy2p[1] = pack2(qy2[2], qy2[3]);
        qz2p[0] = pack2(qz2[0], qz2[1]);  qz2p[1] = pack2(qz2[2], qz2[3]);
        sqp[0]  = pack2(sq[0],  sq[1]);   sqp[1]  = pack2(sq[2],  sq[3]);
    }

    float best[QPT];
    int   bidx[QPT];
#pragma unroll
    for (int t = 0; t < QPT; t++) {
        best[t] = __int_as_float(0x7f800000);  // +inf
        bidx[t] = 0;
    }

    const u64t* sU = reinterpret_cast<const u64t*>(sDup);

    const int r0 = h * RLEN;
    for (int base = r0; base < r0 + RLEN; base += TILE) {
        __syncthreads();
        for (int m = tid; m < TILE; m += THREADS) {
            const float* p = B + ((long)n * NP + base + m) * 3;
            const float bx = p[0], by = p[1], bz = p[2];
            const float bw = norm2_ref(bx, by, bz);
            sDup[2 * m]     = make_float4(bx, bx, by, by);
            sDup[2 * m + 1] = make_float4(bz, bz, bw, bw);
        }
        __syncthreads();

#pragma unroll 8
        for (int j = 0; j < TILE; j++) {
            // broadcast LDS.128 x2: (bxx, byy), (bzz, bww)
            const u64t bxx = sU[4 * j + 0];
            const u64t byy = sU[4 * j + 1];
            const u64t bzz = sU[4 * j + 2];
            const u64t bww = sU[4 * j + 3];
            const int  jg  = base + j;
#pragma unroll
            for (int pp = 0; pp < 2; pp++) {
                u64t m  = mul2(qx2p[pp], bxx);        // rnd(-2x*bx) pairwise
                m       = fma2(qy2p[pp], byy, m);
                m       = fma2(qz2p[pp], bzz, m);     // == -2*dot bitwise
                u64t ss = add2(sqp[pp], bww);         // rnd(sq + bw)
                u64t d2 = add2(ss, m);                // rnd(ss - 2*dot)
                float d0, d1;
                unpack2(d2, d0, d1);
                if (d0 < best[2 * pp]) {
                    best[2 * pp] = d0;  bidx[2 * pp] = jg;
                }
                if (d1 < best[2 * pp + 1]) {
                    best[2 * pp + 1] = d1;  bidx[2 * pp + 1] = jg;
                }
            }
        }
    }

    // Candidate slot: dist layout index = dir*NB*NP + n*NP + q
#pragma unroll
    for (int t = 0; t < QPT; t++) {
        const int q = qbase + t * THREADS;
        const int slot = dir * (NB * NP) + n * NP + q;
        g_cd[h * NQ_TOT + slot] = best[t];
        g_ci[h * NQ_TOT + slot] = bidx[t];
    }
}

__global__ void chamfer_merge_kernel(float* __restrict__ out) {
    const int t = blockIdx.x * blockDim.x + threadIdx.x;
    if (t >= NQ_TOT) return;
    float best = g_cd[t];
    int   bi   = g_ci[t];
#pragma unroll
    for (int h = 1; h < RSPLIT; h++) {
        const float d = g_cd[h * NQ_TOT + t];
        if (d < best) {            // strict <, ascending h => first occurrence
            best = d;
            bi   = g_ci[h * NQ_TOT + t];
        }
    }
    out[t]          = best;        // cham_x | cham_y section
    out[NQ_TOT + t] = (float)bi;   // idx_x  | idx_y  section
}

extern "C" void kernel_launch(void* const* d_in, const int* in_sizes, int n_in,
                              void* d_out, int out_size) {
    const float* x = (const float*)d_in[0];
    const float* y = (const float*)d_in[1];
    float* out = (float*)d_out;

    dim3 grid(NP / QPB, NB, 2 * RSPLIT);   // 32 x 4 x 8 = 1024 blocks
    chamfer_main_kernel<<<grid, THREADS>>>(x, y);
    chamfer_merge_kernel<<<NQ_TOT / 256, 256>>>(out);
}

// round 13
// speedup vs baseline: 1.2260x; 1.0004x over previous
#include <cuda_runtime.h>

// ChamferDistance: N=4, P1=P2=8192, D=3.
// out (float32): [cham_x (N*P)] [cham_y (N*P)] [idx_x (N*P)] [idx_y (N*P)]
//
// Bit-exact emulation of the JAX reference (identical to the round-5 passing
// kernel's arithmetic, now vectorized with Blackwell packed f32x2 ops):
//   sq  = ((x*x)+(y*y))+(z*z)                     (separate roundings)
//   m   = fma(-2z,bz, fma(-2y,by, rnd(-2x*bx)))   == -2*dot bitwise
//   d2  = rnd( rnd(sq + bw) + m )
// Argmin: strict <, ascending j (split halves merged in ascending order)
// => first-occurrence, matching jnp.argmin.

#define NB      4
#define NP      8192
#define THREADS 64
#define QPT     4
#define QPB     (THREADS * QPT)     // 256 queries per block
#define RSPLIT  4                   // reference range split
#define RLEN    (NP / RSPLIT)       // 2048
#define TILE    512                 // ref points staged in shared per iter
#define NQ_TOT  (2 * NB * NP)       // 65536 total queries (both directions)

// Candidate scratch: [rsplit][query-slot]
__device__ float g_cd[RSPLIT * NQ_TOT];
__device__ int   g_ci[RSPLIT * NQ_TOT];

typedef unsigned long long u64t;

__device__ __forceinline__ u64t pack2(float lo, float hi) {
    u64t r;
    asm("mov.b64 %0, {%1, %2};" : "=l"(r) : "f"(lo), "f"(hi));
    return r;
}
__device__ __forceinline__ void unpack2(u64t v, float& lo, float& hi) {
    asm("mov.b64 {%0, %1}, %2;" : "=f"(lo), "=f"(hi) : "l"(v));
}
__device__ __forceinline__ u64t mul2(u64t a, u64t b) {
    u64t r;
    asm("mul.rn.f32x2 %0, %1, %2;" : "=l"(r) : "l"(a), "l"(b));
    return r;
}
__device__ __forceinline__ u64t fma2(u64t a, u64t b, u64t c) {
    u64t r;
    asm("fma.rn.f32x2 %0, %1, %2, %3;" : "=l"(r) : "l"(a), "l"(b), "l"(c));
    return r;
}
__device__ __forceinline__ u64t add2(u64t a, u64t b) {
    u64t r;
    asm("add.rn.f32x2 %0, %1, %2;" : "=l"(r) : "l"(a), "l"(b));
    return r;
}

__device__ __forceinline__ float norm2_ref(float x, float y, float z) {
    // ((x*x)+(y*y))+(z*z), each op individually rounded
    float xx = __fmul_rn(x, x);
    float yy = __fmul_rn(y, y);
    float zz = __fmul_rn(z, z);
    return __fadd_rn(__fadd_rn(xx, yy), zz);
}

__global__ __launch_bounds__(THREADS)
void chamfer_main_kernel(const float* __restrict__ x,
                         const float* __restrict__ y) {
    const int n   = blockIdx.y;            // batch
    const int dir = blockIdx.z / RSPLIT;   // 0: x->y, 1: y->x
    const int h   = blockIdx.z % RSPLIT;   // reference half-range id

    const float* A = (dir == 0) ? x : y;   // query cloud
    const float* B = (dir == 0) ? y : x;   // reference cloud

    // Shared: duplicated components, 32B per ref point:
    // sDup[2j]   = (bx, bx, by, by)
    // sDup[2j+1] = (bz, bz, bw, bw)
    __shared__ float4 sDup[TILE * 2];

    const int tid = threadIdx.x;
    const int qbase = blockIdx.x * QPB + tid;

    // Per-thread query state: 4 queries, packed pairwise (t0,t1) and (t2,t3)
    u64t qx2p[2], qy2p[2], qz2p[2], sqp[2];
    {
        float qx2[QPT], qy2[QPT], qz2[QPT], sq[QPT];
#pragma unroll
        for (int t = 0; t < QPT; t++) {
            const int q = qbase + t * THREADS;
            const float* p = A + ((long)n * NP + q) * 3;
            const float px = p[0], py = p[1], pz = p[2];
            qx2[t] = -2.0f * px;              // exact scaling
            qy2[t] = -2.0f * py;
            qz2[t] = -2.0f * pz;
            sq[t]  = norm2_ref(px, py, pz);
        }
        qx2p[0] = pack2(qx2[0], qx2[1]);  qx2p[1] = pack2(qx2[2], qx2[3]);
        qy2p[0] = pack2(qy2[0], qy2[1]);  qy2p[1] = pack2(qy2[2], qy2[3]);
        qz2p[0] = pack2(qz2[0], qz2[1]);  qz2p[1] = pack2(qz2[2], qz2[3]);
        sqp[0]  = pack2(sq[0],  sq[1]);   sqp[1]  = pack2(sq[2],  sq[3]);
    }

    float best[QPT];
    int   bidx[QPT];
#pragma unroll
    for (int t = 0; t < QPT; t++) {
        best[t] = __int_as_float(0x7f800000);  // +inf
        bidx[t] = 0;
    }

    const u64t* sU = reinterpret_cast<const u64t*>(sDup);

    const int r0 = h * RLEN;
    for (int base = r0; base < r0 + RLEN; base += TILE) {
        __syncthreads();
        for (int m = tid; m < TILE; m += THREADS) {
            const float* p = B + ((long)n * NP + base + m) * 3;
            const float bx = p[0], by = p[1], bz = p[2];
            const float bw = norm2_ref(bx, by, bz);
            sDup[2 * m]     = make_float4(bx, bx, by, by);
            sDup[2 * m + 1] = make_float4(bz, bz, bw, bw);
        }
        __syncthreads();

#pragma unroll 8
        for (int j = 0; j < TILE; j++) {
            // broadcast LDS.128 x2: (bxx, byy), (bzz, bww)
            const u64t bxx = sU[4 * j + 0];
            const u64t byy = sU[4 * j + 1];
            const u64t bzz = sU[4 * j + 2];
            const u64t bww = sU[4 * j + 3];
            const int  jg  = base + j;
#pragma unroll
            for (int pp = 0; pp < 2; pp++) {
                u64t m  = mul2(qx2p[pp], bxx);        // rnd(-2x*bx) pairwise
                m       = fma2(qy2p[pp], byy, m);
                m       = fma2(qz2p[pp], bzz, m);     // == -2*dot bitwise
                u64t ss = add2(sqp[pp], bww);         // rnd(sq + bw)
                u64t d2 = add2(ss, m);                // rnd(ss - 2*dot)
                float d0, d1;
                unpack2(d2, d0, d1);
                if (d0 < best[2 * pp]) {
                    best[2 * pp] = d0;  bidx[2 * pp] = jg;
                }
                if (d1 < best[2 * pp + 1]) {
                    best[2 * pp + 1] = d1;  bidx[2 * pp + 1] = jg;
                }
            }
        }
    }

    // Candidate slot: dist layout index = dir*NB*NP + n*NP + q
#pragma unroll
    for (int t = 0; t < QPT; t++) {
        const int q = qbase + t * THREADS;
        const int slot = dir * (NB * NP) + n * NP + q;
        g_cd[h * NQ_TOT + slot] = best[t];
        g_ci[h * NQ_TOT + slot] = bidx[t];
    }
}

__global__ void chamfer_merge_kernel(float* __restrict__ out) {
    const int t = blockIdx.x * blockDim.x + threadIdx.x;
    if (t >= NQ_TOT) return;
    float best = g_cd[t];
    int   bi   = g_ci[t];
#pragma unroll
    for (int h = 1; h < RSPLIT; h++) {
        const float d = g_cd[h * NQ_TOT + t];
        if (d < best) {            // strict <, ascending h => first occurrence
            best = d;
            bi   = g_ci[h * NQ_TOT + t];
        }
    }
    out[t]          = best;        // cham_x | cham_y section
    out[NQ_TOT + t] = (float)bi;   // idx_x  | idx_y  section
}

extern "C" void kernel_launch(void* const* d_in, const int* in_sizes, int n_in,
                              void* d_out, int out_size) {
    const float* x = (const float*)d_in[0];
    const float* y = (const float*)d_in[1];
    float* out = (float*)d_out;

    dim3 grid(NP / QPB, NB, 2 * RSPLIT);   // 32 x 4 x 8 = 1024 blocks
    chamfer_main_kernel<<<grid, THREADS>>>(x, y);
    chamfer_merge_kernel<<<NQ_TOT / 256, 256>>>(out);
}

// round 15
// speedup vs baseline: 1.2285x; 1.0020x over previous
#include <cuda_runtime.h>

// ChamferDistance: N=4, P1=P2=8192, D=3.
// out (float32): [cham_x (N*P)] [cham_y (N*P)] [idx_x (N*P)] [idx_y (N*P)]
//
// Bit-exact emulation of the JAX reference (identical to the round-5 passing
// kernel's arithmetic, now vectorized with Blackwell packed f32x2 ops):
//   sq  = ((x*x)+(y*y))+(z*z)                     (separate roundings)
//   m   = fma(-2z,bz, fma(-2y,by, rnd(-2x*bx)))   == -2*dot bitwise
//   d2  = rnd( rnd(sq + bw) + m )
// Argmin: strict <, ascending j (split halves merged in ascending order)
// => first-occurrence, matching jnp.argmin.

#define NB      4
#define NP      8192
#define THREADS 64
#define QPT     4
#define QPB     (THREADS * QPT)     // 256 queries per block
#define RSPLIT  4                   // reference range split
#define RLEN    (NP / RSPLIT)       // 2048
#define TILE    512                 // ref points staged in shared per iter
#define NQ_TOT  (2 * NB * NP)       // 65536 total queries (both directions)

// Candidate scratch: [rsplit][query-slot]
__device__ float g_cd[RSPLIT * NQ_TOT];
__device__ int   g_ci[RSPLIT * NQ_TOT];

typedef unsigned long long u64t;

__device__ __forceinline__ u64t pack2(float lo, float hi) {
    u64t r;
    asm("mov.b64 %0, {%1, %2};" : "=l"(r) : "f"(lo), "f"(hi));
    return r;
}
__device__ __forceinline__ void unpack2(u64t v, float& lo, float& hi) {
    asm("mov.b64 {%0, %1}, %2;" : "=f"(lo), "=f"(hi) : "l"(v));
}
__device__ __forceinline__ u64t mul2(u64t a, u64t b) {
    u64t r;
    asm("mul.rn.f32x2 %0, %1, %2;" : "=l"(r) : "l"(a), "l"(b));
    return r;
}
__device__ __forceinline__ u64t fma2(u64t a, u64t b, u64t c) {
    u64t r;
    asm("fma.rn.f32x2 %0, %1, %2, %3;" : "=l"(r) : "l"(a), "l"(b), "l"(c));
    return r;
}
__device__ __forceinline__ u64t add2(u64t a, u64t b) {
    u64t r;
    asm("add.rn.f32x2 %0, %1, %2;" : "=l"(r) : "l"(a), "l"(b));
    return r;
}

__device__ __forceinline__ float norm2_ref(float x, float y, float z) {
    // ((x*x)+(y*y))+(z*z), each op individually rounded
    float xx = __fmul_rn(x, x);
    float yy = __fmul_rn(y, y);
    float zz = __fmul_rn(z, z);
    return __fadd_rn(__fadd_rn(xx, yy), zz);
}

__global__ __launch_bounds__(THREADS)
void chamfer_main_kernel(const float* __restrict__ x,
                         const float* __restrict__ y) {
    const int n   = blockIdx.y;            // batch
    const int dir = blockIdx.z / RSPLIT;   // 0: x->y, 1: y->x
    const int h   = blockIdx.z % RSPLIT;   // reference half-range id

    const float* A = (dir == 0) ? x : y;   // query cloud
    const float* B = (dir == 0) ? y : x;   // reference cloud

    // Shared: duplicated components, 32B per ref point:
    // sDup[2j]   = (bx, bx, by, by)
    // sDup[2j+1] = (bz, bz, bw, bw)
    __shared__ float4 sDup[TILE * 2];

    const int tid = threadIdx.x;
    const int qbase = blockIdx.x * QPB + tid;

    // Per-thread query state: 4 queries, packed pairwise (t0,t1) and (t2,t3)
    u64t qx2p[2], qy2p[2], qz2p[2], sqp[2];
    {
        float qx2[QPT], qy2[QPT], qz2[QPT], sq[QPT];
#pragma unroll
        for (int t = 0; t < QPT; t++) {
            const int q = qbase + t * THREADS;
            const float* p = A + ((long)n * NP + q) * 3;
            const float px = p[0], py = p[1], pz = p[2];
            qx2[t] = -2.0f * px;              // exact scaling
            qy2[t] = -2.0f * py;
            qz2[t] = -2.0f * pz;
            sq[t]  = norm2_ref(px, py, pz);
        }
        qx2p[0] = pack2(qx2[0], qx2[1]);  qx2p[1] = pack2(qx2[2], qx2[3]);
        qy2p[0] = pack2(qy2[0], qy2[1]);  qy2p[1] = pack2(qy2[2], qy2[3]);
        qz2p[0] = pack2(qz2[0], qz2[1]);  qz2p[1] = pack2(qz2[2], qz2[3]);
        sqp[0]  = pack2(sq[0],  sq[1]);   sqp[1]  = pack2(sq[2],  sq[3]);
    }

    float best[QPT];
    int   bidx[QPT];
#pragma unroll
    for (int t = 0; t < QPT; t++) {
        best[t] = __int_as_float(0x7f800000);  // +inf
        bidx[t] = 0;
    }

    const u64t* sU = reinterpret_cast<const u64t*>(sDup);

    const int r0 = h * RLEN;
    for (int base = r0; base < r0 + RLEN; base += TILE) {
        __syncthreads();
        for (int m = tid; m < TILE; m += THREADS) {
            const float* p = B + ((long)n * NP + base + m) * 3;
            const float bx = p[0], by = p[1], bz = p[2];
            const float bw = norm2_ref(bx, by, bz);
            sDup[2 * m]     = make_float4(bx, bx, by, by);
            sDup[2 * m + 1] = make_float4(bz, bz, bw, bw);
        }
        __syncthreads();

#pragma unroll 8
        for (int j = 0; j < TILE; j++) {
            // broadcast LDS.128 x2: (bxx, byy), (bzz, bww)
            const u64t bxx = sU[4 * j + 0];
            const u64t byy = sU[4 * j + 1];
            const u64t bzz = sU[4 * j + 2];
            const u64t bww = sU[4 * j + 3];
            const int  jg  = base + j;
#pragma unroll
            for (int pp = 0; pp < 2; pp++) {
                u64t m  = mul2(qx2p[pp], bxx);        // rnd(-2x*bx) pairwise
                m       = fma2(qy2p[pp], byy, m);
                m       = fma2(qz2p[pp], bzz, m);     // == -2*dot bitwise
                u64t ss = add2(sqp[pp], bww);         // rnd(sq + bw)
                u64t d2 = add2(ss, m);                // rnd(ss - 2*dot)
                float d0, d1;
                unpack2(d2, d0, d1);
                if (d0 < best[2 * pp]) {
                    best[2 * pp] = d0;  bidx[2 * pp] = jg;
                }
                if (d1 < best[2 * pp + 1]) {
                    best[2 * pp + 1] = d1;  bidx[2 * pp + 1] = jg;
                }
            }
        }
    }

    // Candidate slot: dist layout index = dir*NB*NP + n*NP + q
#pragma unroll
    for (int t = 0; t < QPT; t++) {
        const int q = qbase + t * THREADS;
        const int slot = dir * (NB * NP) + n * NP + q;
        g_cd[h * NQ_TOT + slot] = best[t];
        g_ci[h * NQ_TOT + slot] = bidx[t];
    }
}

__global__ void chamfer_merge_kernel(float* __restrict__ out) {
    const int t = blockIdx.x * blockDim.x + threadIdx.x;
    if (t >= NQ_TOT) return;
    float best = g_cd[t];
    int   bi   = g_ci[t];
#pragma unroll
    for (int h = 1; h < RSPLIT; h++) {
        const float d = g_cd[h * NQ_TOT + t];
        if (d < best) {            // strict <, ascending h => first occurrence
            best = d;
            bi   = g_ci[h * NQ_TOT + t];
        }
    }
    out[t]          = best;        // cham_x | cham_y section
    out[NQ_TOT + t] = (float)bi;   // idx_x  | idx_y  section
}

extern "C" void kernel_launch(void* const* d_in, const int* in_sizes, int n_in,
                              void* d_out, int out_size) {
    const float* x = (const float*)d_in[0];
    const float* y = (const float*)d_in[1];
    float* out = (float*)d_out;

    dim3 grid(NP / QPB, NB, 2 * RSPLIT);   // 32 x 4 x 8 = 1024 blocks
    chamfer_main_kernel<<<grid, THREADS>>>(x, y);
    chamfer_merge_kernel<<<NQ_TOT / 256, 256>>>(out);
}